// round 7
// baseline (speedup 1.0000x reference)
#include <cuda_runtime.h>

#define B_  128
#define T_  256
#define R_  1024
#define NU_ 256
#define BR_ (B_*R_)

// ---------------- static device scratch ----------------
// state tensors TRANSPOSED: [r][b]
__device__ float g_xh[(size_t)T_*BR_];    // [t][r][b]
__device__ float g_xt[(size_t)T_*BR_];    // [t][r][b]
__device__ float g_hist[(size_t)T_*BR_];  // [t][r][b]
__device__ float g_sA[BR_];
__device__ float g_sB[BR_];
__device__ float g_s0[BR_];               // stays zero

typedef unsigned long long u64;

__device__ __forceinline__ u64 pk2(float lo, float hi) {
    u64 r; asm("mov.b64 %0, {%1, %2};" : "=l"(r) : "f"(lo), "f"(hi)); return r;
}
__device__ __forceinline__ void up2(float &lo, float &hi, u64 v) {
    asm("mov.b64 {%0, %1}, %2;" : "=f"(lo), "=f"(hi) : "l"(v));
}
__device__ __forceinline__ void fma2(u64 &d, u64 a, u64 b) {
    asm("fma.rn.f32x2 %0, %1, %2, %0;" : "+l"(d) : "l"(a), "l"(b));
}
__device__ __forceinline__ u64 add2(u64 a, u64 b) {
    u64 r; asm("add.rn.f32x2 %0, %1, %2;" : "=l"(r) : "l"(a), "l"(b)); return r;
}

__device__ __forceinline__ float sigmoid_(float x) {
    return __frcp_rn(1.f + __expf(-x));
}
__device__ __forceinline__ float tanh_(float x) {
    return __fmaf_rn(2.f, __frcp_rn(1.f + __expf(-2.f*x)), -1.f);
}

__device__ __forceinline__ void cp16(unsigned s, const void* g) {
    asm volatile("cp.async.cg.shared.global [%0], [%1], 16;" :: "r"(s), "l"(g));
}
__device__ __forceinline__ void cpcommit() { asm volatile("cp.async.commit_group;"); }
template<int N> __device__ __forceinline__ void cpwait() {
    asm volatile("cp.async.wait_group %0;" :: "n"(N));
}
// named barrier over 64 threads (one kq-pair); ids 1..8
__device__ __forceinline__ void pairbar(int id) {
    asm volatile("bar.sync %0, 64;" :: "r"(id) : "memory");
}

// =================================================================================
// Stage kernel: one highway layer, tensors [r][b].
// 512 threads = 16 warps = (kq 8) x (gate 2); 4 warps/SMSP.
// Warp: full 128m x 8n tile of its gate for a 128-k eighth (thread 8m x 4n).
// NO block barriers in mainloop: each kq-pair streams its own eighth into a
// PRIVATE double-buffered smem region via its own cp.async groups; the two
// gate-warps sync via named barrier (64 threads). Pairs drift freely.
// Inner loop per k: 2 LDS.128 (s) + 1 LDS.128 (w) + 4 mov dup + 16 FFMA2.
// Dyn smem: w plain 64 KB | s 8 pairs x 2 bufs x 8 KB = 128 KB -> 192 KB.
// Reduction/tg alias the s region after a single block sync.
// =================================================================================
#define KCW 16                        // k per chunk per eighth
#define NCHW 8                        // chunks (128/16)
#define SM_WP        0                // + gate*32768 + k*32 + half*16
#define SM_SD(q,buf) (65536 + (q)*16384 + (buf)*8192)
#define SM_RED       65536            // aliases s (after mainloop sync)
#define SM_TG        122880           // aliases s
#define SM_TOTAL     196608           // 192 KB

__global__ __launch_bounds__(512, 1) void stage_kernel(
    const float* __restrict__ s_in,
    const float* __restrict__ Wh, const float* __restrict__ Wt,
    const float* __restrict__ addh, const float* __restrict__ addt,
    int per_elem,
    float* __restrict__ s_out)
{
    extern __shared__ char sm[];
    const int tid  = threadIdx.x;
    const int n0   = blockIdx.x * 8;
    const int warp = tid >> 5, lane = tid & 31;
    const int kq   = warp >> 1, gate = warp & 1;
    const int mg   = lane & 15, ng = lane >> 4;
    const int mA   = mg * 4;
    const int mB   = 64 + mg * 4;
    const int pidx = gate * 32 + lane;          // 0..63 within pair
    const int barid = kq + 1;
    const unsigned smb = (unsigned)__cvta_generic_to_shared(sm);

    // ---- prologue group0: plain weights (4096 cp16) + s chunk0 (own eighth) ----
    #pragma unroll
    for (int it = 0; it < 8; ++it) {
        int idx = tid + it*512;                 // 0..4095
        int mat  = idx >> 11;                   // 0 = Wh, 1 = Wt
        int k    = (idx >> 1) & 1023;
        int half = idx & 1;
        const float* src = (mat ? Wt : Wh) + (size_t)k*R_ + n0 + half*4;
        cp16(smb + SM_WP + mat*32768 + k*32 + half*16, src);
    }
    {
        const char* g = (const char*)s_in + (size_t)(kq*128)*512;
        #pragma unroll
        for (int j = 0; j < 8; ++j) {
            int off = pidx*128 + j*16;
            cp16(smb + SM_SD(kq,0) + off, g + off);
        }
    }
    cpcommit();
    // ---- prologue group1: s chunk1 ----
    {
        const char* g = (const char*)s_in + (size_t)(kq*128 + KCW)*512;
        #pragma unroll
        for (int j = 0; j < 8; ++j) {
            int off = pidx*128 + j*16;
            cp16(smb + SM_SD(kq,1) + off, g + off);
        }
    }
    cpcommit();
    cpwait<1>();          // group0 done (w portion + own s chunk0)
    __syncthreads();      // all threads' w contributions visible

    u64 acc[16];
    #pragma unroll
    for (int a = 0; a < 16; ++a) acc[a] = 0;

    const char* wgbase = sm + SM_WP + gate*32768 + ng*16;

    #pragma unroll
    for (int c = 0; c < NCHW; ++c) {
        // ---- compute chunk c from buf c&1 ----
        const char* sp = sm + SM_SD(kq, c & 1) + mg*16;
        const char* wp = wgbase + (size_t)(kq*128 + c*KCW)*32;
        #pragma unroll
        for (int kl = 0; kl < KCW; ++kl) {
            ulonglong2 sA2 = *(const ulonglong2*)(sp + kl*512);
            ulonglong2 sB2 = *(const ulonglong2*)(sp + kl*512 + 256);
            float4 w4 = *(const float4*)(wp + kl*32);
            u64 w0 = pk2(w4.x, w4.x), w1 = pk2(w4.y, w4.y);
            u64 w2 = pk2(w4.z, w4.z), w3 = pk2(w4.w, w4.w);
            fma2(acc[0],  sA2.x, w0); fma2(acc[1],  sA2.y, w0);
            fma2(acc[2],  sB2.x, w0); fma2(acc[3],  sB2.y, w0);
            fma2(acc[4],  sA2.x, w1); fma2(acc[5],  sA2.y, w1);
            fma2(acc[6],  sB2.x, w1); fma2(acc[7],  sB2.y, w1);
            fma2(acc[8],  sA2.x, w2); fma2(acc[9],  sA2.y, w2);
            fma2(acc[10], sB2.x, w2); fma2(acc[11], sB2.y, w2);
            fma2(acc[12], sA2.x, w3); fma2(acc[13], sA2.y, w3);
            fma2(acc[14], sB2.x, w3); fma2(acc[15], sB2.y, w3);
        }
        // ---- pair-private pipeline maintenance ----
        if (c + 2 < NCHW) {
            pairbar(barid);   // both warps done reading buf c&1 -> safe to overwrite
            const char* g = (const char*)s_in + (size_t)(kq*128 + (c+2)*KCW)*512;
            #pragma unroll
            for (int j = 0; j < 8; ++j) {
                int off = pidx*128 + j*16;
                cp16(smb + SM_SD(kq, c & 1) + off, g + off);
            }
            cpcommit();
        }
        if (c + 1 < NCHW) {
            if (c + 2 < NCHW) cpwait<1>(); else cpwait<0>();
            pairbar(barid);   // data for chunk c+1 visible to both warps
        }
    }
    __syncthreads();   // protect s region before aliasing as red/tg

    // ---- cross-eighth reduction (red aliases s) ----
    u64* red = (u64*)(sm + SM_RED);
    if (kq > 0) {
        u64* dst = red + (size_t)(((kq-1)*2 + gate)*32 + lane)*16;
        #pragma unroll
        for (int a = 0; a < 16; ++a) dst[a] = acc[a];
    }
    __syncthreads();
    if (kq == 0) {
        #pragma unroll
        for (int r = 0; r < 7; ++r) {
            const u64* src = red + (size_t)((r*2 + gate)*32 + lane)*16;
            #pragma unroll
            for (int a = 0; a < 16; ++a) acc[a] = add2(acc[a], src[a]);
        }
    }

    // ---- epilogue (kq0 warps): gate1 sigmoid -> tg; gate0 combines ----
    float* tg = (float*)(sm + SM_TG);
    if (kq == 0 && gate == 1) {
        #pragma unroll
        for (int j = 0; j < 4; ++j) {
            int n = n0 + ng*4 + j;
            float v[8];
            up2(v[0], v[1], acc[j*4+0]); up2(v[2], v[3], acc[j*4+1]);
            up2(v[4], v[5], acc[j*4+2]); up2(v[6], v[7], acc[j*4+3]);
            float4 tA, tB;
            if (per_elem) {
                tA = *(const float4*)(addt + (size_t)n*128 + mA);
                tB = *(const float4*)(addt + (size_t)n*128 + mB);
            } else {
                float bv = addt[n];
                tA = make_float4(bv, bv, bv, bv); tB = tA;
            }
            float4 oA, oB;
            oA.x = sigmoid_(v[0] + tA.x); oA.y = sigmoid_(v[1] + tA.y);
            oA.z = sigmoid_(v[2] + tA.z); oA.w = sigmoid_(v[3] + tA.w);
            oB.x = sigmoid_(v[4] + tB.x); oB.y = sigmoid_(v[5] + tB.y);
            oB.z = sigmoid_(v[6] + tB.z); oB.w = sigmoid_(v[7] + tB.w);
            *(float4*)&tg[(ng*4+j)*128 + mA] = oA;
            *(float4*)&tg[(ng*4+j)*128 + mB] = oB;
        }
    }
    __syncthreads();
    if (kq == 0 && gate == 0) {
        #pragma unroll
        for (int j = 0; j < 4; ++j) {
            int n = n0 + ng*4 + j;
            float v[8];
            up2(v[0], v[1], acc[j*4+0]); up2(v[2], v[3], acc[j*4+1]);
            up2(v[4], v[5], acc[j*4+2]); up2(v[6], v[7], acc[j*4+3]);
            float4 hA, hB;
            if (per_elem) {
                hA = *(const float4*)(addh + (size_t)n*128 + mA);
                hB = *(const float4*)(addh + (size_t)n*128 + mB);
            } else {
                float bv = addh[n];
                hA = make_float4(bv, bv, bv, bv); hB = hA;
            }
            float4 tgA = *(float4*)&tg[(ng*4+j)*128 + mA];
            float4 tgB = *(float4*)&tg[(ng*4+j)*128 + mB];
            float4 svA = *(const float4*)(s_in + (size_t)n*128 + mA);
            float4 svB = *(const float4*)(s_in + (size_t)n*128 + mB);
            float4 oA, oB;
            oA.x = (tanh_(v[0] + hA.x) - svA.x) * tgA.x + svA.x;
            oA.y = (tanh_(v[1] + hA.y) - svA.y) * tgA.y + svA.y;
            oA.z = (tanh_(v[2] + hA.z) - svA.z) * tgA.z + svA.z;
            oA.w = (tanh_(v[3] + hA.w) - svA.w) * tgA.w + svA.w;
            oB.x = (tanh_(v[4] + hB.x) - svB.x) * tgB.x + svB.x;
            oB.y = (tanh_(v[5] + hB.y) - svB.y) * tgB.y + svB.y;
            oB.z = (tanh_(v[6] + hB.z) - svB.z) * tgB.z + svB.z;
            oB.w = (tanh_(v[7] + hB.w) - svB.w) * tgB.w + svB.w;
            *(float4*)(s_out + (size_t)n*128 + mA) = oA;
            *(float4*)(s_out + (size_t)n*128 + mB) = oB;
        }
    }
}

// =================================================================================
// Pre kernel: xh = emb[tok]@Wh0x + bh0 ; xt = emb[tok]@Wt0x + bt0, stored [t][r][b].
// =================================================================================
#define KBP 8
__global__ __launch_bounds__(256, 1) void pre_kernel(
    const int* __restrict__ tok, const float* __restrict__ emb,
    const float* __restrict__ Whx, const float* __restrict__ Wtx,
    const float* __restrict__ bh, const float* __restrict__ bt)
{
    __shared__ float x_sm[NU_*34];
    __shared__ u64 wh_sm[KBP*64];
    __shared__ u64 wt_sm[KBP*64];

    const int tid  = threadIdx.x;
    const int row0 = blockIdx.y * 32;
    const int n0   = blockIdx.x * 64;

    #pragma unroll
    for (int it = 0; it < 8; ++it) {
        int idx = tid + it*256;
        int r = idx >> 6, q = idx & 63;
        int rho = row0 + r;
        int b = rho & (B_-1), t = rho >> 7;
        int token = tok[b*T_ + t];
        float4 v = *(const float4*)(emb + (size_t)token*NU_ + 4*q);
        x_sm[(4*q+0)*34 + r] = v.x;
        x_sm[(4*q+1)*34 + r] = v.y;
        x_sm[(4*q+2)*34 + r] = v.z;
        x_sm[(4*q+3)*34 + r] = v.w;
    }
    __syncthreads();

    const int mp = tid & 15;
    const int ng = tid >> 4;
    u64 acch[4] = {0,0,0,0};
    u64 acct[4] = {0,0,0,0};

    for (int k0 = 0; k0 < NU_; k0 += KBP) {
        #pragma unroll
        for (int it = 0; it < 2; ++it) {
            int idx = tid + it*256;
            int kl = idx >> 6, c = idx & 63;
            float wh = Whx[(size_t)(k0+kl)*R_ + n0 + c];
            float wt = Wtx[(size_t)(k0+kl)*R_ + n0 + c];
            wh_sm[kl*64 + c] = pk2(wh, wh);
            wt_sm[kl*64 + c] = pk2(wt, wt);
        }
        __syncthreads();
        #pragma unroll
        for (int kl = 0; kl < KBP; ++kl) {
            u64 x2 = *(const u64*)&x_sm[(k0+kl)*34 + 2*mp];
            ulonglong2 wa = *(const ulonglong2*)&wh_sm[kl*64 + 4*ng];
            ulonglong2 wb = *(const ulonglong2*)&wh_sm[kl*64 + 4*ng + 2];
            ulonglong2 ta = *(const ulonglong2*)&wt_sm[kl*64 + 4*ng];
            ulonglong2 tb = *(const ulonglong2*)&wt_sm[kl*64 + 4*ng + 2];
            fma2(acch[0], x2, wa.x); fma2(acch[1], x2, wa.y);
            fma2(acch[2], x2, wb.x); fma2(acch[3], x2, wb.y);
            fma2(acct[0], x2, ta.x); fma2(acct[1], x2, ta.y);
            fma2(acct[2], x2, tb.x); fma2(acct[3], x2, tb.y);
        }
        __syncthreads();
    }

    #pragma unroll
    for (int j = 0; j < 4; ++j) {
        int n = n0 + 4*ng + j;
        float lo, hi, tlo, thi;
        up2(lo, hi, acch[j]);
        up2(tlo, thi, acct[j]);
        int rho = row0 + 2*mp;
        int b = rho & (B_-1), t = rho >> 7;
        size_t base = (size_t)t*BR_ + (size_t)n*128 + b;
        g_xh[base]   = lo  + bh[n];
        g_xh[base+1] = hi  + bh[n];
        g_xt[base]   = tlo + bt[n];
        g_xt[base+1] = thi + bt[n];
    }
}

// =================================================================================
// Post kernel: out[(b*T+t), n] = sum_k hist[t][k][b] * Wp[k][n] + bp[n].
// =================================================================================
#define KBQ 32
__global__ __launch_bounds__(256, 1) void post_kernel(
    const float* __restrict__ Wp, const float* __restrict__ bp,
    float* __restrict__ out)
{
    __shared__ float s_sm[KBQ*32];
    __shared__ u64 w_sm[KBQ*64];

    const int tid = threadIdx.x;
    const int n0  = blockIdx.x * 64;
    const int b0  = blockIdx.y * 32;
    const int t   = blockIdx.z;
    const float* A = g_hist + (size_t)t*BR_;

    const int mp = tid & 15;
    const int ng = tid >> 4;
    u64 acc[4] = {0,0,0,0};

    for (int k0 = 0; k0 < R_; k0 += KBQ) {
        {
            int kl = tid >> 3, bl = (tid & 7) * 4;
            float4 v = *(const float4*)(A + (size_t)(k0+kl)*128 + b0 + bl);
            *(float4*)&s_sm[kl*32 + bl] = v;
        }
        #pragma unroll
        for (int it = 0; it < 4; ++it) {
            int idx = tid + it*256;
            int kl = idx >> 5, c = idx & 31;
            float2 wv = *(const float2*)(Wp + (size_t)(k0+kl)*NU_ + n0 + 2*c);
            w_sm[kl*64 + 2*c]   = pk2(wv.x, wv.x);
            w_sm[kl*64 + 2*c+1] = pk2(wv.y, wv.y);
        }
        __syncthreads();
        #pragma unroll 8
        for (int kl = 0; kl < KBQ; ++kl) {
            u64 s2 = *(const u64*)&s_sm[kl*32 + 2*mp];
            ulonglong2 wa = *(const ulonglong2*)&w_sm[kl*64 + 4*ng];
            ulonglong2 wb = *(const ulonglong2*)&w_sm[kl*64 + 4*ng + 2];
            fma2(acc[0], s2, wa.x); fma2(acc[1], s2, wa.y);
            fma2(acc[2], s2, wb.x); fma2(acc[3], s2, wb.y);
        }
        __syncthreads();
    }

    #pragma unroll
    for (int j = 0; j < 4; ++j) {
        int n = n0 + 4*ng + j;
        float lo, hi;
        up2(lo, hi, acc[j]);
        int bl = b0 + 2*mp;
        out[(size_t)(bl*T_ + t)*NU_ + n]     = lo + bp[n];
        out[(size_t)((bl+1)*T_ + t)*NU_ + n] = hi + bp[n];
    }
}

// =================================================================================
extern "C" void kernel_launch(void* const* d_in, const int* in_sizes, int n_in,
                              void* d_out, int out_size) {
    const int*   tok  = (const int*)  d_in[0];
    const float* emb  = (const float*)d_in[1];
    const float* Wh0x = (const float*)d_in[2];
    const float* Wh0s = (const float*)d_in[3];
    const float* bh0  = (const float*)d_in[4];
    const float* Wt0x = (const float*)d_in[5];
    const float* Wt0s = (const float*)d_in[6];
    const float* bt0  = (const float*)d_in[7];
    const float* Whh  = (const float*)d_in[8];
    const float* bhh  = (const float*)d_in[9];
    const float* Wth  = (const float*)d_in[10];
    const float* bth  = (const float*)d_in[11];
    const float* Wp   = (const float*)d_in[12];
    const float* bp   = (const float*)d_in[13];

    float *xh, *xt, *hist, *sA, *sB, *s0;
    cudaGetSymbolAddress((void**)&xh,   g_xh);
    cudaGetSymbolAddress((void**)&xt,   g_xt);
    cudaGetSymbolAddress((void**)&hist, g_hist);
    cudaGetSymbolAddress((void**)&sA,   g_sA);
    cudaGetSymbolAddress((void**)&sB,   g_sB);
    cudaGetSymbolAddress((void**)&s0,   g_s0);

    cudaFuncSetAttribute(stage_kernel,
                         cudaFuncAttributeMaxDynamicSharedMemorySize, SM_TOTAL);

    pre_kernel<<<dim3(16, 1024), 256>>>(tok, emb, Wh0x, Wt0x, bh0, bt0);

    const float* sprev = s0;
    for (int t = 0; t < T_; ++t) {
        stage_kernel<<<128, 512, SM_TOTAL>>>(sprev, Wh0s, Wt0s,
                                             xh + (size_t)t*BR_, xt + (size_t)t*BR_,
                                             1, sA);
        stage_kernel<<<128, 512, SM_TOTAL>>>(sA, Whh, Wth, bhh, bth, 0, sB);
        stage_kernel<<<128, 512, SM_TOTAL>>>(sB, Whh + (size_t)R_*R_, Wth + (size_t)R_*R_,
                                             bhh + R_, bth + R_, 0,
                                             hist + (size_t)t*BR_);
        sprev = hist + (size_t)t*BR_;
    }

    post_kernel<<<dim3(4, 4, 256), 256>>>(Wp, bp, (float*)d_out);
}

// round 10
// speedup vs baseline: 1.3750x; 1.3750x over previous
#include <cuda_runtime.h>
#include <cuda_bf16.h>

#define B_  128
#define T_  256
#define R_  1024
#define NU_ 256
#define BR_ (B_*R_)
#define KEXT 3072

typedef unsigned long long u64;
typedef unsigned int u32;

// ---------------- static device scratch ----------------
__device__ float g_xh[(size_t)T_*BR_];    // [t][r][b]
__device__ float g_xt[(size_t)T_*BR_];    // [t][r][b]
__device__ float g_hist[(size_t)T_*BR_];  // [t][r][b]
__device__ float g_sA[BR_];
__device__ float g_sB[BR_];
__device__ float g_s0[BR_];               // zeros
// extended-K bf16 weights: [mat][n][3072] = [W_hi | W_lo | W_hi] along k
// mats: Wh0s,Wt0s,Whh0,Wth0,Whh1,Wth1
__device__ __nv_bfloat16 g_wq[6u*1024u*KEXT];
// bf16 split state ping-pong, [m][k] row-major
__device__ __nv_bfloat16 g_shi[2][BR_];
__device__ __nv_bfloat16 g_slo[2][BR_];
__device__ __nv_bfloat16 g_shz[BR_];      // zeros
__device__ __nv_bfloat16 g_slz[BR_];      // zeros

// ---------------- helpers ----------------
__device__ __forceinline__ u64 pk2(float lo, float hi) {
    u64 r; asm("mov.b64 %0, {%1, %2};" : "=l"(r) : "f"(lo), "f"(hi)); return r;
}
__device__ __forceinline__ void up2(float &lo, float &hi, u64 v) {
    asm("mov.b64 {%0, %1}, %2;" : "=f"(lo), "=f"(hi) : "l"(v));
}
__device__ __forceinline__ void fma2(u64 &d, u64 a, u64 b) {
    asm("fma.rn.f32x2 %0, %1, %2, %0;" : "+l"(d) : "l"(a), "l"(b));
}
__device__ __forceinline__ float sigmoid_(float x) { return __frcp_rn(1.f + __expf(-x)); }
__device__ __forceinline__ float tanh_(float x) {
    return __fmaf_rn(2.f, __frcp_rn(1.f + __expf(-2.f*x)), -1.f);
}
__device__ __forceinline__ void cp16(unsigned s, const void* g) {
    asm volatile("cp.async.cg.shared.global [%0], [%1], 16;" :: "r"(s), "l"(g));
}
__device__ __forceinline__ void cpcommit() { asm volatile("cp.async.commit_group;"); }
template<int N> __device__ __forceinline__ void cpwait() {
    asm volatile("cp.async.wait_group %0;" :: "n"(N));
}
__device__ __forceinline__ u32 smem_u32(const void* p) {
    u32 a; asm("{ .reg .u64 t; cvta.to.shared.u64 t, %1; cvt.u32.u64 %0, t; }" : "=r"(a) : "l"(p));
    return a;
}

#define LDM4(r0,r1,r2,r3,addr) \
    asm volatile("ldmatrix.sync.aligned.m8n8.x4.shared.b16 {%0,%1,%2,%3}, [%4];" \
        : "=r"(r0),"=r"(r1),"=r"(r2),"=r"(r3) : "r"(addr))

#define MMA16816(c0,c1,c2,c3,a0,a1,a2,a3,b0,b1) \
    asm volatile("mma.sync.aligned.m16n8k16.row.col.f32.bf16.bf16.f32 " \
        "{%0,%1,%2,%3}, {%4,%5,%6,%7}, {%8,%9}, {%0,%1,%2,%3};" \
        : "+f"(c0),"+f"(c1),"+f"(c2),"+f"(c3) \
        : "r"(a0),"r"(a1),"r"(a2),"r"(a3),"r"(b0),"r"(b1))

// =================================================================================
// Stage kernel (mma.sync bf16): one highway layer.
//   G[m, j]    = sum_kext A_ext[m,kext] Wh_ext[n0+j, kext]   (j 0..15, h-gate)
//   G[m, 16+j] = likewise with Wt_ext                         (t-gate)
// A_ext = [s_hi | s_hi | s_lo] along k (3-term bf16 split, fp32 accumulate).
// Grid 64 x 16 n-cols. 256 threads = 8 warps (warp = 16 m x 32 n).
// K streamed in 24 chunks of 128, triple-buffered cp.async, 1 sync/chunk.
// SMEM rows padded to 272 B -> cp.async 16B aligned + ldmatrix conflict-free.
// =================================================================================
#define KC 128
#define NCH 24
#define PITCH 272
#define A_BYTES (128*PITCH)       // 34816
#define B_BYTES (32*PITCH)        // 8704
#define BUF_BYTES (A_BYTES + B_BYTES)
#define SM_A(p) ((p)*BUF_BYTES)
#define SM_B(p) ((p)*BUF_BYTES + A_BYTES)
#define SM_TOTAL (3*BUF_BYTES)    // 130560

__global__ __launch_bounds__(256, 1)
void stage_tc(const float* __restrict__ s_in,
              const __nv_bfloat16* __restrict__ shi_in,
              const __nv_bfloat16* __restrict__ slo_in,
              const __nv_bfloat16* __restrict__ wh_ext,
              const __nv_bfloat16* __restrict__ wt_ext,
              const float* __restrict__ addh, const float* __restrict__ addt,
              int per_elem,
              float* __restrict__ s_out,
              __nv_bfloat16* __restrict__ shi_out,
              __nv_bfloat16* __restrict__ slo_out)
{
    extern __shared__ char sm[];
    const int tid  = threadIdx.x;
    const int warp = tid >> 5, lane = tid & 31;
    const int n0   = blockIdx.x * 16;
    const int M0   = warp * 16;
    const u32 smb  = smem_u32(sm);

    // ---------------- chunk loader ----------------
    auto load_chunk = [&](int c, int p) {
        const int seg = c >> 3;                 // 0,1 -> s_hi ; 2 -> s_lo
        const int k0  = (c & 7) * KC;
        const __nv_bfloat16* asrc = (seg == 2) ? slo_in : shi_in;
        #pragma unroll
        for (int it = 0; it < 8; ++it) {        // A: 128 rows x 128 k = 2048 cp16
            int idx = tid + it*256;
            int m = idx >> 4, kin = (idx & 15) * 8;
            cp16(smb + SM_A(p) + m*PITCH + kin*2,
                 asrc + (size_t)m*R_ + k0 + kin);
        }
        #pragma unroll
        for (int it = 0; it < 2; ++it) {        // B: 32 rows x 128 k = 512 cp16
            int idx = tid + it*256;
            int row = idx >> 4, kin = (idx & 15) * 8;
            const __nv_bfloat16* bsrc = (row < 16) ? wh_ext : wt_ext;
            cp16(smb + SM_B(p) + row*PITCH + kin*2,
                 bsrc + (size_t)(n0 + (row & 15))*KEXT + c*KC + kin);
        }
        cpcommit();
    };

    load_chunk(0, 0);
    load_chunk(1, 1);

    float acc[16];
    #pragma unroll
    for (int a = 0; a < 16; ++a) acc[a] = 0.f;

    const u32 arow = (M0 + (lane & 15))*PITCH + (lane >> 4)*16;
    const u32 brow0 = (lane & 15)*PITCH + (lane >> 4)*16;        // B rows 0-15
    const u32 brow1 = (16 + (lane & 15))*PITCH + (lane >> 4)*16; // B rows 16-31

    for (int c = 0; c < NCH; ++c) {
        if (c < NCH-1) cpwait<1>(); else cpwait<0>();
        __syncthreads();
        if (c + 2 < NCH) load_chunk(c + 2, (c + 2) % 3);

        const int p = c % 3;
        const u32 abase = smb + SM_A(p) + arow;
        const u32 bbase0 = smb + SM_B(p) + brow0;
        const u32 bbase1 = smb + SM_B(p) + brow1;
        #pragma unroll
        for (int ks = 0; ks < 8; ++ks) {
            u32 a0,a1,a2,a3, p0,p1,p2,p3, q0,q1,q2,q3;
            LDM4(a0,a1,a2,a3, abase + ks*32);
            LDM4(p0,p1,p2,p3, bbase0 + ks*32);   // n-tiles 0,1 (h cols 0-15)
            LDM4(q0,q1,q2,q3, bbase1 + ks*32);   // n-tiles 2,3 (t cols 0-15)
            MMA16816(acc[0], acc[1], acc[2], acc[3],  a0,a1,a2,a3, p0,p2);
            MMA16816(acc[4], acc[5], acc[6], acc[7],  a0,a1,a2,a3, p1,p3);
            MMA16816(acc[8], acc[9], acc[10],acc[11], a0,a1,a2,a3, q0,q2);
            MMA16816(acc[12],acc[13],acc[14],acc[15], a0,a1,a2,a3, q1,q3);
        }
    }
    __syncthreads();   // all reads done; buffers reusable for staging

    // ---------------- stage D to smem (Gsm aliases A buf0) ----------------
    float* Gsm = (float*)(sm + SM_A(0));        // [128][34]
    {
        const int r = lane >> 2, cb = (lane & 3)*2;
        #pragma unroll
        for (int nt = 0; nt < 4; ++nt) {
            *(float2*)&Gsm[(M0 + r)*34 + nt*8 + cb]     = make_float2(acc[nt*4+0], acc[nt*4+1]);
            *(float2*)&Gsm[(M0 + r + 8)*34 + nt*8 + cb] = make_float2(acc[nt*4+2], acc[nt*4+3]);
        }
    }
    __syncthreads();

    // ---------------- highway epilogue (coalesced) ----------------
    float* Ssm = (float*)(sm + SM_B(0));        // [128][17]
    {
        const int m = tid & 127, jh = tid >> 7;
        #pragma unroll
        for (int jj = 0; jj < 8; ++jj) {
            int j = jh*8 + jj;
            int n = n0 + j;
            float gh = Gsm[m*34 + j];
            float gt = Gsm[m*34 + 16 + j];
            float ah = per_elem ? addh[(size_t)n*128 + m] : addh[n];
            float at = per_elem ? addt[(size_t)n*128 + m] : addt[n];
            float so = s_in[(size_t)n*128 + m];
            float h  = tanh_(gh + ah);
            float tg = sigmoid_(gt + at);
            float sn = (h - so)*tg + so;
            s_out[(size_t)n*128 + m] = sn;
            Ssm[m*17 + j] = sn;
        }
    }
    __syncthreads();

    // ---------------- bf16 hi/lo write ([m][k], 32B per row) ----------------
    if (tid < 128) {
        const int m = tid;
        u32 uh[8], ul[8];
        #pragma unroll
        for (int j = 0; j < 16; ++j) {
            float sn = Ssm[m*17 + j];
            __nv_bfloat16 hi = __float2bfloat16(sn);
            __nv_bfloat16 lo = __float2bfloat16(sn - __bfloat162float(hi));
            unsigned short hs = __bfloat16_as_ushort(hi);
            unsigned short ls = __bfloat16_as_ushort(lo);
            if (j & 1) { uh[j >> 1] |= ((u32)hs) << 16; ul[j >> 1] |= ((u32)ls) << 16; }
            else       { uh[j >> 1]  = hs;              ul[j >> 1]  = ls; }
        }
        *(uint4*)(shi_out + (size_t)m*R_ + n0)     = make_uint4(uh[0], uh[1], uh[2], uh[3]);
        *(uint4*)(shi_out + (size_t)m*R_ + n0 + 8) = make_uint4(uh[4], uh[5], uh[6], uh[7]);
        *(uint4*)(slo_out + (size_t)m*R_ + n0)     = make_uint4(ul[0], ul[1], ul[2], ul[3]);
        *(uint4*)(slo_out + (size_t)m*R_ + n0 + 8) = make_uint4(ul[4], ul[5], ul[6], ul[7]);
    }
}

// =================================================================================
// Weight prep: transpose + bf16 hi/lo split into extended-K layout [n][3072].
// =================================================================================
__global__ __launch_bounds__(256, 1) void wprep(
    const float* __restrict__ W0, const float* __restrict__ W1,
    const float* __restrict__ W2, const float* __restrict__ W3,
    const float* __restrict__ W4, const float* __restrict__ W5)
{
    __shared__ float tile[32][33];
    const int z = blockIdx.z;
    const float* W = (z == 0) ? W0 : (z == 1) ? W1 : (z == 2) ? W2
                   : (z == 3) ? W3 : (z == 4) ? W4 : W5;
    const int k0 = blockIdx.x * 32, n0 = blockIdx.y * 32;
    const int tx = threadIdx.x & 31, ty = threadIdx.x >> 5;
    #pragma unroll
    for (int r = 0; r < 4; ++r) {
        int kk = ty + r*8;
        tile[kk][tx] = W[(size_t)(k0 + kk)*R_ + n0 + tx];
    }
    __syncthreads();
    #pragma unroll
    for (int r = 0; r < 4; ++r) {
        int nn = ty + r*8;
        float v = tile[tx][nn];
        __nv_bfloat16 hi = __float2bfloat16(v);
        __nv_bfloat16 lo = __float2bfloat16(v - __bfloat162float(hi));
        size_t base = (size_t)z*1024u*KEXT + (size_t)(n0 + nn)*KEXT;
        g_wq[base + k0 + tx]        = hi;
        g_wq[base + 1024 + k0 + tx] = lo;
        g_wq[base + 2048 + k0 + tx] = hi;
    }
}

// =================================================================================
// Pre kernel: xh = emb[tok]@Wh0x + bh0 ; xt likewise, stored [t][r][b].
// =================================================================================
#define KBP 8
__global__ __launch_bounds__(256, 1) void pre_kernel(
    const int* __restrict__ tok, const float* __restrict__ emb,
    const float* __restrict__ Whx, const float* __restrict__ Wtx,
    const float* __restrict__ bh, const float* __restrict__ bt)
{
    __shared__ float x_sm[NU_*34];
    __shared__ u64 wh_sm[KBP*64];
    __shared__ u64 wt_sm[KBP*64];

    const int tid  = threadIdx.x;
    const int row0 = blockIdx.y * 32;
    const int n0   = blockIdx.x * 64;

    #pragma unroll
    for (int it = 0; it < 8; ++it) {
        int idx = tid + it*256;
        int r = idx >> 6, q = idx & 63;
        int rho = row0 + r;
        int b = rho & (B_-1), t = rho >> 7;
        int token = tok[b*T_ + t];
        float4 v = *(const float4*)(emb + (size_t)token*NU_ + 4*q);
        x_sm[(4*q+0)*34 + r] = v.x;
        x_sm[(4*q+1)*34 + r] = v.y;
        x_sm[(4*q+2)*34 + r] = v.z;
        x_sm[(4*q+3)*34 + r] = v.w;
    }
    __syncthreads();

    const int mp = tid & 15;
    const int ng = tid >> 4;
    u64 acch[4] = {0,0,0,0};
    u64 acct[4] = {0,0,0,0};

    for (int k0 = 0; k0 < NU_; k0 += KBP) {
        #pragma unroll
        for (int it = 0; it < 2; ++it) {
            int idx = tid + it*256;
            int kl = idx >> 6, c = idx & 63;
            float wh = Whx[(size_t)(k0+kl)*R_ + n0 + c];
            float wt = Wtx[(size_t)(k0+kl)*R_ + n0 + c];
            wh_sm[kl*64 + c] = pk2(wh, wh);
            wt_sm[kl*64 + c] = pk2(wt, wt);
        }
        __syncthreads();
        #pragma unroll
        for (int kl = 0; kl < KBP; ++kl) {
            u64 x2 = *(const u64*)&x_sm[(k0+kl)*34 + 2*mp];
            ulonglong2 wa = *(const ulonglong2*)&wh_sm[kl*64 + 4*ng];
            ulonglong2 wb = *(const ulonglong2*)&wh_sm[kl*64 + 4*ng + 2];
            ulonglong2 ta = *(const ulonglong2*)&wt_sm[kl*64 + 4*ng];
            ulonglong2 tb = *(const ulonglong2*)&wt_sm[kl*64 + 4*ng + 2];
            fma2(acch[0], x2, wa.x); fma2(acch[1], x2, wa.y);
            fma2(acch[2], x2, wb.x); fma2(acch[3], x2, wb.y);
            fma2(acct[0], x2, ta.x); fma2(acct[1], x2, ta.y);
            fma2(acct[2], x2, tb.x); fma2(acct[3], x2, tb.y);
        }
        __syncthreads();
    }

    #pragma unroll
    for (int j = 0; j < 4; ++j) {
        int n = n0 + 4*ng + j;
        float lo, hi, tlo, thi;
        up2(lo, hi, acch[j]);
        up2(tlo, thi, acct[j]);
        int rho = row0 + 2*mp;
        int b = rho & (B_-1), t = rho >> 7;
        size_t base = (size_t)t*BR_ + (size_t)n*128 + b;
        g_xh[base]   = lo  + bh[n];
        g_xh[base+1] = hi  + bh[n];
        g_xt[base]   = tlo + bt[n];
        g_xt[base+1] = thi + bt[n];
    }
}

// =================================================================================
// Post kernel: out[(b*T+t), n] = sum_k hist[t][k][b] * Wp[k][n] + bp[n].
// =================================================================================
#define KBQ 32
__global__ __launch_bounds__(256, 1) void post_kernel(
    const float* __restrict__ Wp, const float* __restrict__ bp,
    float* __restrict__ out)
{
    __shared__ float s_sm[KBQ*32];
    __shared__ u64 w_sm[KBQ*64];

    const int tid = threadIdx.x;
    const int n0  = blockIdx.x * 64;
    const int b0  = blockIdx.y * 32;
    const int t   = blockIdx.z;
    const float* A = g_hist + (size_t)t*BR_;

    const int mp = tid & 15;
    const int ng = tid >> 4;
    u64 acc[4] = {0,0,0,0};

    for (int k0 = 0; k0 < R_; k0 += KBQ) {
        {
            int kl = tid >> 3, bl = (tid & 7) * 4;
            float4 v = *(const float4*)(A + (size_t)(k0+kl)*128 + b0 + bl);
            *(float4*)&s_sm[kl*32 + bl] = v;
        }
        #pragma unroll
        for (int it = 0; it < 4; ++it) {
            int idx = tid + it*256;
            int kl = idx >> 5, c = idx & 31;
            float2 wv = *(const float2*)(Wp + (size_t)(k0+kl)*NU_ + n0 + 2*c);
            w_sm[kl*64 + 2*c]   = pk2(wv.x, wv.x);
            w_sm[kl*64 + 2*c+1] = pk2(wv.y, wv.y);
        }
        __syncthreads();
        #pragma unroll 8
        for (int kl = 0; kl < KBQ; ++kl) {
            u64 s2 = *(const u64*)&s_sm[kl*32 + 2*mp];
            ulonglong2 wa = *(const ulonglong2*)&w_sm[kl*64 + 4*ng];
            ulonglong2 wb = *(const ulonglong2*)&w_sm[kl*64 + 4*ng + 2];
            fma2(acc[0], s2, wa.x); fma2(acc[1], s2, wa.y);
            fma2(acc[2], s2, wb.x); fma2(acc[3], s2, wb.y);
        }
        __syncthreads();
    }

    #pragma unroll
    for (int j = 0; j < 4; ++j) {
        int n = n0 + 4*ng + j;
        float lo, hi;
        up2(lo, hi, acc[j]);
        int bl = b0 + 2*mp;
        out[(size_t)(bl*T_ + t)*NU_ + n]     = lo + bp[n];
        out[(size_t)((bl+1)*T_ + t)*NU_ + n] = hi + bp[n];
    }
}

// =================================================================================
extern "C" void kernel_launch(void* const* d_in, const int* in_sizes, int n_in,
                              void* d_out, int out_size) {
    const int*   tok  = (const int*)  d_in[0];
    const float* emb  = (const float*)d_in[1];
    const float* Wh0x = (const float*)d_in[2];
    const float* Wh0s = (const float*)d_in[3];
    const float* bh0  = (const float*)d_in[4];
    const float* Wt0x = (const float*)d_in[5];
    const float* Wt0s = (const float*)d_in[6];
    const float* bt0  = (const float*)d_in[7];
    const float* Whh  = (const float*)d_in[8];
    const float* bhh  = (const float*)d_in[9];
    const float* Wth  = (const float*)d_in[10];
    const float* bth  = (const float*)d_in[11];
    const float* Wp   = (const float*)d_in[12];
    const float* bp   = (const float*)d_in[13];

    float *xh, *xt, *hist, *sA, *sB, *s0;
    __nv_bfloat16 *wq, *shi0, *slo0, *shz, *slz;
    cudaGetSymbolAddress((void**)&xh,   g_xh);
    cudaGetSymbolAddress((void**)&xt,   g_xt);
    cudaGetSymbolAddress((void**)&hist, g_hist);
    cudaGetSymbolAddress((void**)&sA,   g_sA);
    cudaGetSymbolAddress((void**)&sB,   g_sB);
    cudaGetSymbolAddress((void**)&s0,   g_s0);
    cudaGetSymbolAddress((void**)&wq,   g_wq);
    cudaGetSymbolAddress((void**)&shi0, g_shi);
    cudaGetSymbolAddress((void**)&slo0, g_slo);
    cudaGetSymbolAddress((void**)&shz,  g_shz);
    cudaGetSymbolAddress((void**)&slz,  g_slz);

    cudaFuncSetAttribute(stage_tc, cudaFuncAttributeMaxDynamicSharedMemorySize, SM_TOTAL);

    wprep<<<dim3(32, 32, 6), 256>>>(Wh0s, Wt0s, Whh, Wth,
                                    Whh + 1048576, Wth + 1048576);
    pre_kernel<<<dim3(16, 1024), 256>>>(tok, emb, Wh0x, Wt0x, bh0, bt0);

    const float* sf_in = s0;
    const __nv_bfloat16* bhi_in = shz;
    const __nv_bfloat16* blo_in = slz;
    int si = 0;
    for (int t = 0; t < T_; ++t) {
        for (int layer = 0; layer < 3; ++layer) {
            float* sf_out = (layer == 0) ? sA : (layer == 1) ? sB : hist + (size_t)t*BR_;
            int mh = (layer == 0) ? 0 : (layer == 1) ? 2 : 4;
            int mt = mh + 1;
            const float* ah = (layer == 0) ? xh + (size_t)t*BR_ : bhh + (layer-1)*R_;
            const float* at = (layer == 0) ? xt + (size_t)t*BR_ : bth + (layer-1)*R_;
            int pe = (layer == 0) ? 1 : 0;
            __nv_bfloat16* bhi_out = shi0 + (size_t)(si & 1)*BR_;
            __nv_bfloat16* blo_out = slo0 + (size_t)(si & 1)*BR_;
            stage_tc<<<64, 256, SM_TOTAL>>>(
                sf_in, bhi_in, blo_in,
                wq + (size_t)mh*1024u*KEXT,
                wq + (size_t)mt*1024u*KEXT,
                ah, at, pe, sf_out, bhi_out, blo_out);
            sf_in = sf_out; bhi_in = bhi_out; blo_in = blo_out;
            ++si;
        }
    }

    post_kernel<<<dim3(4, 4, 256), 256>>>(Wp, bp, (float*)d_out);
}